// round 16
// baseline (speedup 1.0000x reference)
#include <cuda_runtime.h>
#include <cuda_bf16.h>
#include <math.h>
#include <stdint.h>

#define B_   32
#define J_   16384
#define D_   32
#define H_   128
#define EH_  256
#define EPS_ 1e-5f

#define MM_BLOCKS 592
#define NPAIR (J_ / 2)      // 8192
#define PITCH 272           // bytes per A-tile row (128 bf16 = 256B + 16B pad)
#define A_LO_OFF 17408      // 64 rows * 272
#define PJT 16

typedef unsigned long long ull;

// ---- static device scratch ----
__device__ float g_pre1[J_ * H_];        // precg[j][k] = (pre - mean)*g1[k]
__device__ float g_sppc[J_], g_spwc[J_];
__device__ ull   g_wb[H_];               // [2p]=(wcg_2p,wcg_2p+1) [2p+1]=(B1_2p,B1_2p+1)
__device__ float g_swwc;
__device__ ull   g_wfrag[64 * 32];       // B fragments: [seg(2)][kt(8)][nt(4)][lane(32)]
__device__ float g_part[MM_BLOCKS * B_ * D_];
__device__ float g_cnt[MM_BLOCKS * B_];
__device__ float g_xT[J_ * B_];
__device__ float g_mT[J_ * B_];

// ---- helpers ----
__device__ __forceinline__ ull ffma2(ull a, ull b, ull c) {
    ull d; asm("fma.rn.f32x2 %0, %1, %2, %3;" : "=l"(d) : "l"(a), "l"(b), "l"(c)); return d;
}
__device__ __forceinline__ ull pack2(float v) {
    ull r; asm("mov.b64 %0, {%1, %1};" : "=l"(r) : "f"(v)); return r;
}
__device__ __forceinline__ ull packf(float a, float b) {
    ull r; asm("mov.b64 %0, {%1, %2};" : "=l"(r) : "f"(a), "f"(b)); return r;
}
#define UNPK(lo, hi, v) asm("mov.b64 {%0, %1}, %2;" : "=f"(lo), "=f"(hi) : "l"(v))

__device__ __forceinline__ uint32_t smem_u32(const void* p) {
    uint32_t a;
    asm("{ .reg .u64 t; cvta.to.shared.u64 t, %1; cvt.u32.u64 %0, t; }" : "=r"(a) : "l"(p));
    return a;
}
__device__ __forceinline__ uint32_t cvt_bf16x2(float fe, float fo) {
    uint32_t r; asm("cvt.rn.bf16x2.f32 %0, %1, %2;" : "=r"(r) : "f"(fo), "f"(fe)); return r;
}

#define LDSM4(r, addr) \
    asm volatile("ldmatrix.sync.aligned.m8n8.x4.shared.b16 {%0,%1,%2,%3}, [%4];" \
        : "=r"((r)[0]), "=r"((r)[1]), "=r"((r)[2]), "=r"((r)[3]) : "r"(addr))

__device__ __forceinline__ void mma_bf16(float* c, const uint32_t* a, uint32_t b0, uint32_t b1) {
    asm volatile("mma.sync.aligned.m16n8k16.row.col.f32.bf16.bf16.f32 "
        "{%0,%1,%2,%3}, {%4,%5,%6,%7}, {%8,%9}, {%0,%1,%2,%3};"
        : "+f"(c[0]), "+f"(c[1]), "+f"(c[2]), "+f"(c[3])
        : "r"(a[0]), "r"(a[1]), "r"(a[2]), "r"(a[3]), "r"(b0), "r"(b1));
}

// ============================================================
// Kernel A (fused front): blocks 0..511 xpose; block 512 wfrag;
// blocks 513..1536 k_pre body (threads 128..255 duplicate 0..127,
// all writes idempotent-same-value).
// ============================================================
__global__ __launch_bounds__(256) void k_front_pre(
    const float* __restrict__ x, const int* __restrict__ mask,
    const float* __restrict__ hW2,
    const float* __restrict__ feat_emb, const float* __restrict__ atse_emb,
    const int* __restrict__ atse_idx, const float* __restrict__ hW1,
    const float* __restrict__ hb1, const float* __restrict__ hg1,
    const float* __restrict__ hB1)
{
    __shared__ float tx[32][33];
    __shared__ float tm[32][33];
    __shared__ __align__(16) float sfeat[PJT][48];
    __shared__ int sidx[PJT];
    __shared__ __align__(16) float sP[PJT][H_];
    __shared__ __align__(16) float sw0c[H_];
    __shared__ float sred[4];

    int t = threadIdx.x;
    if (blockIdx.x < 512) {
        int jbase = blockIdx.x * 32;
        #pragma unroll
        for (int r = 0; r < 4; r++) {
            int b  = (t >> 5) + r * 8;
            int jj = t & 31;
            tx[b][jj] = x[b * J_ + jbase + jj];
            tm[b][jj] = (float)mask[b * J_ + jbase + jj];
        }
        __syncthreads();
        #pragma unroll
        for (int r = 0; r < 4; r++) {
            int jj = (t >> 5) + r * 8;
            int b  = t & 31;
            g_xT[(jbase + jj) * B_ + b] = tx[b][jj];
            g_mT[(jbase + jj) * B_ + b] = tm[b][jj];
        }
        return;
    }
    if (blockIdx.x == 512) {
        for (int e = t; e < 2048; e += 256) {
            int s = e >> 5, lane = e & 31;
            int seg = s >> 5, kt = (s >> 2) & 7, nt = s & 3;
            int k0 = kt * 16 + (lane & 3) * 2;
            int n  = nt * 8 + (lane >> 2);
            float v[4];
            v[0] = hW2[k0 * 32 + n];
            v[1] = hW2[(k0 + 1) * 32 + n];
            v[2] = hW2[(k0 + 8) * 32 + n];
            v[3] = hW2[(k0 + 9) * 32 + n];
            float sv[4];
            #pragma unroll
            for (int i = 0; i < 4; i++) {
                float vh = __bfloat162float(__float2bfloat16(v[i]));
                sv[i] = (seg == 0) ? vh : (v[i] - vh);
            }
            uint32_t b0 = cvt_bf16x2(sv[0], sv[1]);
            uint32_t b1 = cvt_bf16x2(sv[2], sv[3]);
            g_wfrag[e] = (ull)b0 | ((ull)b1 << 32);
        }
        return;
    }

    // ---- k_pre body; k in [0,128), upper half duplicates lower ----
    int k = t & 127;
    int w = k >> 5, lane = k & 31;
    int jbase = (int)(blockIdx.x - 513) * PJT;

    float wv = hW1[k];
    float s = wv;
    #pragma unroll
    for (int o = 16; o; o >>= 1) s += __shfl_xor_sync(0xffffffffu, s, o);
    if (lane == 0) sred[w] = s;   // warps 4..7 write same values as 0..3
    if (k < PJT) sidx[k] = atse_idx[jbase + k];
    __syncthreads();
    float mean0 = (sred[0] + sred[1] + sred[2] + sred[3]) * (1.f / H_);
    float w0c = wv - mean0;
    sw0c[k] = w0c;
    if (blockIdx.x == 513) {
        float ss = w0c * w0c;
        #pragma unroll
        for (int o = 16; o; o >>= 1) ss += __shfl_xor_sync(0xffffffffu, ss, o);
        __syncthreads();
        if (lane == 0) sred[w] = ss;
        __syncthreads();
        if (k == 0) g_swwc = sred[0] + sred[1] + sred[2] + sred[3];
        if (k < 64) {
            g_wb[2 * k]     = packf(sw0c[2 * k] * hg1[2 * k], sw0c[2 * k + 1] * hg1[2 * k + 1]);
            g_wb[2 * k + 1] = packf(hB1[2 * k], hB1[2 * k + 1]);
        }
    }

    for (int e = k; e < PJT * 48; e += 128) {
        int jj = e / 48, i = e % 48;
        sfeat[jj][i] = (i < 32) ? feat_emb[(jbase + jj) * 32 + i]
                                : atse_emb[sidx[jj] * 16 + (i - 32)];
    }

    ull wp[24];
    #pragma unroll
    for (int ip = 0; ip < 24; ip++)
        wp[ip] = packf(hW1[(1 + 2 * ip) * H_ + k], hW1[(2 + 2 * ip) * H_ + k]);
    float bk = hb1[k];
    __syncthreads();

    #pragma unroll 2
    for (int jj = 0; jj < PJT; jj++) {
        ull a0 = packf(bk, 0.f), a1 = packf(0.f, 0.f);
        const ull* f = (const ull*)&sfeat[jj][0];
        #pragma unroll
        for (int ip = 0; ip < 12; ip++) {
            a0 = ffma2(f[ip], wp[ip], a0);
            a1 = ffma2(f[ip + 12], wp[ip + 12], a1);
        }
        float l0, h0, l1, h1;
        UNPK(l0, h0, a0); UNPK(l1, h1, a1);
        sP[jj][k] = (l0 + h0) + (l1 + h1);
    }
    __syncthreads();

    #pragma unroll
    for (int r = 0; r < PJT / 4; r++) {
        int jj = w + 4 * r;
        int j = jbase + jj;
        float4 p4 = *(const float4*)&sP[jj][lane * 4];
        float sp = p4.x + p4.y + p4.z + p4.w;
        #pragma unroll
        for (int o = 16; o; o >>= 1) sp += __shfl_xor_sync(0xffffffffu, sp, o);
        float mval = sp * (1.f / H_);
        float c0 = p4.x - mval, c1 = p4.y - mval, c2 = p4.z - mval, c3 = p4.w - mval;
        float4 w4 = *(const float4*)&sw0c[lane * 4];
        float4 g4 = *(const float4*)&hg1[lane * 4];
        float4 pg; pg.x = c0 * g4.x; pg.y = c1 * g4.y; pg.z = c2 * g4.z; pg.w = c3 * g4.w;
        *(float4*)&g_pre1[j * H_ + lane * 4] = pg;     // duplicated same-value store
        float ss = c0 * c0 + c1 * c1 + c2 * c2 + c3 * c3;
        float sw = c0 * w4.x + c1 * w4.y + c2 * w4.z + c3 * w4.w;
        #pragma unroll
        for (int o = 16; o; o >>= 1) {
            ss += __shfl_xor_sync(0xffffffffu, ss, o);
            sw += __shfl_xor_sync(0xffffffffu, sw, o);
        }
        if (lane == 0) { g_sppc[j] = ss; g_spwc[j] = sw; }
    }
}

// ============================================================
// Kernel C (hot, mma.sync): block = 64 thr (2 warps). warp <-> one j,
// lane <-> b. 3-term bf16 split on HMMA. Epilogue on fragments.
// (byte-identical to the 84.4us champion)
// ============================================================
__global__ __launch_bounds__(64) void k_main_mma(
    const float* __restrict__ hb2,
    const float* __restrict__ hg2, const float* __restrict__ hB2)
{
    __shared__ __align__(16) char sA[2 * 64 * PITCH];
    __shared__ __align__(16) float spre[2][H_];
    __shared__ __align__(16) ull  swb[H_];

    int t = threadIdx.x, w = t >> 5, lane = t & 31;
    int g = lane >> 2, tg = lane & 3;

    for (int e = t; e < H_; e += 64) swb[e] = g_wb[e];

    float hb2v[8], g2v[8], B2v[8];
    #pragma unroll
    for (int i = 0; i < 8; i++) {
        int d = (i >> 1) * 8 + tg * 2 + (i & 1);
        hb2v[i] = __ldg(hb2 + d);
        g2v[i]  = __ldg(hg2 + d);
        B2v[i]  = __ldg(hB2 + d);
    }
    float swwc = g_swwc;

    uint32_t sA_u = smem_u32(sA);
    char* rowHp = sA + (w * 32 + lane) * PITCH;
    char* rowLp = rowHp + A_LO_OFF;
    uint32_t lmB0 = sA_u + (w * 32 + (lane & 15)) * PITCH + ((lane >> 4) << 4);
    uint32_t lmB1 = lmB0 + 16 * PITCH;

    float poolA[2][8], poolB[2][8];
    #pragma unroll
    for (int mt = 0; mt < 2; mt++)
        #pragma unroll
        for (int i = 0; i < 8; i++) { poolA[mt][i] = 0.f; poolB[mt][i] = 0.f; }
    float cacc[2][2] = {{0.f, 0.f}, {0.f, 0.f}};

    __syncthreads();

    for (int jp = blockIdx.x; jp < NPAIR; jp += MM_BLOCKS) {
        int j = 2 * jp + w;
        float4 p4 = ((const float4*)(g_pre1 + j * H_))[lane];
        *(float4*)((char*)spre[w] + lane * 16) = p4;
        float xb = g_xT[j * B_ + lane];
        float ev = fmaf(xb, fmaf(xb, swwc, 2.f * g_spwc[j]), g_sppc[j]) * (1.f / H_);
        float rs = rsqrtf(ev + EPS_);
        ull xb2 = pack2(xb), rs2 = pack2(rs);
        __syncwarp();

        const ull* pre = (const ull*)spre[w];
        #pragma unroll
        for (int q = 0; q < 16; q++) {
            uint32_t hw[4], lw[4];
            #pragma unroll
            for (int pp = 0; pp < 4; pp++) {
                int p = q * 4 + pp;
                ull tt = ffma2(xb2, swb[2 * p], pre[p]);
                ull hf = ffma2(tt, rs2, swb[2 * p + 1]);
                float f0, f1; UNPK(f0, f1, hf);
                f0 = fmaxf(f0, 0.f); f1 = fmaxf(f1, 0.f);
                uint32_t hi = cvt_bf16x2(f0, f1);
                float d0 = __uint_as_float(hi << 16);
                float d1 = __uint_as_float(hi & 0xFFFF0000u);
                lw[pp] = cvt_bf16x2(f0 - d0, f1 - d1);
                hw[pp] = hi;
            }
            *(uint4*)(rowHp + q * 16) = make_uint4(hw[0], hw[1], hw[2], hw[3]);
            *(uint4*)(rowLp + q * 16) = make_uint4(lw[0], lw[1], lw[2], lw[3]);
        }
        __syncwarp();

        float dacc[2][4][4];
        #pragma unroll
        for (int mt = 0; mt < 2; mt++)
            #pragma unroll
            for (int nt = 0; nt < 4; nt++)
                #pragma unroll
                for (int c = 0; c < 4; c++) dacc[mt][nt][c] = 0.f;

        #pragma unroll
        for (int kt = 0; kt < 8; kt++) {
            uint32_t ah0[4], ah1[4], al0[4], al1[4];
            LDSM4(ah0, lmB0 + kt * 32);
            LDSM4(ah1, lmB1 + kt * 32);
            LDSM4(al0, lmB0 + A_LO_OFF + kt * 32);
            LDSM4(al1, lmB1 + A_LO_OFF + kt * 32);
            #pragma unroll
            for (int nt = 0; nt < 4; nt++) {
                ull vH = __ldg(&g_wfrag[(kt * 4 + nt) * 32 + lane]);
                ull vL = __ldg(&g_wfrag[(32 + kt * 4 + nt) * 32 + lane]);
                uint32_t bh0 = (uint32_t)vH, bh1 = (uint32_t)(vH >> 32);
                uint32_t bl0 = (uint32_t)vL, bl1 = (uint32_t)(vL >> 32);
                mma_bf16(dacc[0][nt], ah0, bh0, bh1);
                mma_bf16(dacc[0][nt], ah0, bl0, bl1);
                mma_bf16(dacc[0][nt], al0, bh0, bh1);
                mma_bf16(dacc[1][nt], ah1, bh0, bh1);
                mma_bf16(dacc[1][nt], ah1, bl0, bl1);
                mma_bf16(dacc[1][nt], al1, bh0, bh1);
            }
        }

        #pragma unroll
        for (int mt = 0; mt < 2; mt++) {
            float oA[8], oB[8];
            #pragma unroll
            for (int i = 0; i < 8; i++) {
                int nt = i >> 1, c = i & 1;
                oA[i] = dacc[mt][nt][c] + hb2v[i];
                oB[i] = dacc[mt][nt][2 + c] + hb2v[i];
            }
            float s1A = 0.f, s2A = 0.f, s1B = 0.f, s2B = 0.f;
            #pragma unroll
            for (int i = 0; i < 8; i++) {
                s1A += oA[i]; s2A = fmaf(oA[i], oA[i], s2A);
                s1B += oB[i]; s2B = fmaf(oB[i], oB[i], s2B);
            }
            s1A += __shfl_xor_sync(0xffffffffu, s1A, 1);
            s1A += __shfl_xor_sync(0xffffffffu, s1A, 2);
            s2A += __shfl_xor_sync(0xffffffffu, s2A, 1);
            s2A += __shfl_xor_sync(0xffffffffu, s2A, 2);
            s1B += __shfl_xor_sync(0xffffffffu, s1B, 1);
            s1B += __shfl_xor_sync(0xffffffffu, s1B, 2);
            s2B += __shfl_xor_sync(0xffffffffu, s2B, 1);
            s2B += __shfl_xor_sync(0xffffffffu, s2B, 2);
            float mA = s1A * (1.f / 32.f);
            float rA = rsqrtf(s2A * (1.f / 32.f) - mA * mA + EPS_);
            float mB = s1B * (1.f / 32.f);
            float rB = rsqrtf(s2B * (1.f / 32.f) - mB * mB + EPS_);
            float mkA = g_mT[j * B_ + mt * 16 + g];
            float mkB = g_mT[j * B_ + mt * 16 + 8 + g];
            if (tg == 0) { cacc[mt][0] += mkA; cacc[mt][1] += mkB; }
            #pragma unroll
            for (int i = 0; i < 8; i++) {
                float eA = fmaxf(fmaf((oA[i] - mA) * rA, g2v[i], B2v[i]), 0.f);
                float eB = fmaxf(fmaf((oB[i] - mB) * rB, g2v[i], B2v[i]), 0.f);
                poolA[mt][i] = fmaf(mkA, eA, poolA[mt][i]);
                poolB[mt][i] = fmaf(mkB, eB, poolB[mt][i]);
            }
        }
    }

    __syncthreads();
    float* sred = (float*)sA;
    float* scnt = (float*)(sA + 8192);
    #pragma unroll
    for (int i = 0; i < 32; i++) {
        int mt = i >> 4, h = (i >> 3) & 1, ii = i & 7;
        sred[(w * 32 + lane) * 32 + i] = h ? poolB[mt][ii] : poolA[mt][ii];
    }
    if (tg == 0) {
        #pragma unroll
        for (int mt = 0; mt < 2; mt++) {
            scnt[w * 32 + mt * 16 + g]     = cacc[mt][0];
            scnt[w * 32 + mt * 16 + 8 + g] = cacc[mt][1];
        }
    }
    __syncthreads();
    if (w == 0) {
        #pragma unroll
        for (int i = 0; i < 32; i++) {
            float s = sred[lane * 32 + i] + sred[(32 + lane) * 32 + i];
            int mt = i >> 4, h = (i >> 3) & 1, ii = i & 7, nt = ii >> 1, c = ii & 1;
            int b = mt * 16 + (h ? 8 : 0) + g;
            int d = nt * 8 + tg * 2 + c;
            g_part[blockIdx.x * (B_ * D_) + b * D_ + d] = s;
        }
        g_cnt[blockIdx.x * B_ + lane] = scnt[lane] + scnt[32 + lane];
    }
}

// ============================================================
// Kernel D (fused reduce+final): one block per b. Reduce this b's
// slice of g_part/g_cnt (fixed order, deterministic), then encoder MLP.
// ============================================================
__device__ __forceinline__ float block_reduce256(float v, float* red, int t) {
    red[t] = v; __syncthreads();
    #pragma unroll
    for (int s = 128; s > 0; s >>= 1) {
        if (t < s) red[t] += red[t + s];
        __syncthreads();
    }
    float r = red[0]; __syncthreads();
    return r;
}

__global__ __launch_bounds__(256) void k_final(
    const float* __restrict__ eW1, const float* __restrict__ eb1,
    const float* __restrict__ eg1, const float* __restrict__ eB1,
    const float* __restrict__ eW2, const float* __restrict__ eb2,
    const float* __restrict__ eg2, const float* __restrict__ eB2,
    float* __restrict__ out)
{
    int b = blockIdx.x, t = threadIdx.x;
    __shared__ float red[256];
    __shared__ float sraw[D_];
    __shared__ float sc[D_];
    __shared__ float se[EH_];
    __shared__ float sml[64];

    // ---- reduce pooled partials for this b (coalesced, 8 chunks) ----
    int d = t & 31, c = t >> 5;
    float s = 0.f;
    for (int blk = c; blk < MM_BLOCKS; blk += 8)
        s += g_part[blk * (B_ * D_) + b * D_ + d];
    red[t] = s;
    __syncthreads();
    if (c == 0) {
        float tot = 0.f;
        #pragma unroll
        for (int cc = 0; cc < 8; cc++) tot += red[cc * 32 + d];
        sraw[d] = tot;
    }
    __syncthreads();

    // ---- reduce counts for this b ----
    float cm = 0.f;
    for (int blk = t; blk < MM_BLOCKS; blk += 256) cm += g_cnt[blk * B_ + b];
    float cnt = block_reduce256(cm, red, t);

    if (t < D_) sc[t] = sraw[t] / fmaxf(cnt, 1.f);
    __syncthreads();

    // ---- encoder MLP ----
    float pe = eb1[t];
    #pragma unroll
    for (int k = 0; k < D_; k++) pe = fmaf(sc[k], eW1[k * EH_ + t], pe);
    float s1 = block_reduce256(pe, red, t);
    float s2 = block_reduce256(pe * pe, red, t);
    float m  = s1 * (1.f / EH_);
    float v  = s2 * (1.f / EH_) - m * m;
    float rs = rsqrtf(v + EPS_);
    se[t] = fmaxf(fmaf((pe - m) * rs, eg1[t], eB1[t]), 0.f);
    __syncthreads();

    if (t < 64) {
        float pm = eb2[t];
        for (int k = 0; k < EH_; k++) pm = fmaf(se[k], eW2[k * 64 + t], pm);
        sml[t] = pm;
    }
    __syncthreads();
    if (t < 64) {
        float a = 0.f, q = 0.f;
        #pragma unroll
        for (int k = 0; k < 64; k++) { a += sml[k]; q = fmaf(sml[k], sml[k], q); }
        float mm = a * (1.f / 64.f);
        float vv = q * (1.f / 64.f) - mm * mm;
        float rr = rsqrtf(vv + EPS_);
        float ml = fmaxf(fmaf((sml[t] - mm) * rr, eg2[t], eB2[t]), 0.f);
        int off = (t < 32) ? (b * 32 + t) : (B_ * 32 + b * 32 + (t - 32));
        out[off] = ml;
    }
}

// ============================================================
extern "C" void kernel_launch(void* const* d_in, const int* in_sizes, int n_in,
                              void* d_out, int out_size) {
    const float* x         = (const float*)d_in[0];
    const int*   mask      = (const int*)  d_in[1];
    const int*   atse_idx  = (const int*)  d_in[2];
    const float* feat_emb  = (const float*)d_in[3];
    const float* atse_emb  = (const float*)d_in[4];
    const float* hW1       = (const float*)d_in[5];
    const float* hb1       = (const float*)d_in[6];
    const float* hg1       = (const float*)d_in[7];
    const float* hB1       = (const float*)d_in[8];
    const float* hW2       = (const float*)d_in[9];
    const float* hb2       = (const float*)d_in[10];
    const float* hg2       = (const float*)d_in[11];
    const float* hB2       = (const float*)d_in[12];
    const float* eW1       = (const float*)d_in[13];
    const float* eb1       = (const float*)d_in[14];
    const float* eg1       = (const float*)d_in[15];
    const float* eB1       = (const float*)d_in[16];
    const float* eW2       = (const float*)d_in[17];
    const float* eb2       = (const float*)d_in[18];
    const float* eg2       = (const float*)d_in[19];
    const float* eB2       = (const float*)d_in[20];
    float* out = (float*)d_out;

    k_front_pre<<<513 + J_ / PJT, 256>>>(x, mask, hW2, feat_emb, atse_emb,
                                         atse_idx, hW1, hb1, hg1, hB1);
    k_main_mma<<<MM_BLOCKS, 64>>>(hb2, hg2, hB2);
    k_final<<<B_, 256>>>(eW1, eb1, eg1, eB1, eW2, eb2, eg2, eB2, out);
}

// round 17
// speedup vs baseline: 1.1103x; 1.1103x over previous
#include <cuda_runtime.h>
#include <cuda_bf16.h>
#include <math.h>
#include <stdint.h>

#define B_   32
#define J_   16384
#define D_   32
#define H_   128
#define EH_  256
#define EPS_ 1e-5f

#define MM_BLOCKS 592
#define NPAIR (J_ / 2)      // 8192
#define PITCH 272           // bytes per A-tile row (128 bf16 = 256B + 16B pad)
#define A_LO_OFF 17408      // 64 rows * 272
#define PJT 16

typedef unsigned long long ull;

// ---- static device scratch ----
__device__ float g_pre1[J_ * H_];        // precg[j][k] = (pre - mean)*g1[k]
__device__ float g_sppc[J_], g_spwc[J_];
__device__ ull   g_wb[H_];               // [2p]=(wcg_2p,wcg_2p+1) [2p+1]=(B1_2p,B1_2p+1)
__device__ float g_swwc;
__device__ ull   g_wfrag[64 * 32];       // B fragments: [seg(2)][kt(8)][nt(4)][lane(32)]
__device__ float g_part[MM_BLOCKS * B_ * D_];
__device__ float g_cnt[MM_BLOCKS * B_];
__device__ float g_xT[J_ * B_];
__device__ float g_mT[J_ * B_];

// ---- helpers ----
__device__ __forceinline__ ull ffma2(ull a, ull b, ull c) {
    ull d; asm("fma.rn.f32x2 %0, %1, %2, %3;" : "=l"(d) : "l"(a), "l"(b), "l"(c)); return d;
}
__device__ __forceinline__ ull pack2(float v) {
    ull r; asm("mov.b64 %0, {%1, %1};" : "=l"(r) : "f"(v)); return r;
}
__device__ __forceinline__ ull packf(float a, float b) {
    ull r; asm("mov.b64 %0, {%1, %2};" : "=l"(r) : "f"(a), "f"(b)); return r;
}
#define UNPK(lo, hi, v) asm("mov.b64 {%0, %1}, %2;" : "=f"(lo), "=f"(hi) : "l"(v))

__device__ __forceinline__ uint32_t smem_u32(const void* p) {
    uint32_t a;
    asm("{ .reg .u64 t; cvta.to.shared.u64 t, %1; cvt.u32.u64 %0, t; }" : "=r"(a) : "l"(p));
    return a;
}
__device__ __forceinline__ uint32_t cvt_bf16x2(float fe, float fo) {
    uint32_t r; asm("cvt.rn.bf16x2.f32 %0, %1, %2;" : "=r"(r) : "f"(fo), "f"(fe)); return r;
}

#define LDSM4(r, addr) \
    asm volatile("ldmatrix.sync.aligned.m8n8.x4.shared.b16 {%0,%1,%2,%3}, [%4];" \
        : "=r"((r)[0]), "=r"((r)[1]), "=r"((r)[2]), "=r"((r)[3]) : "r"(addr))

__device__ __forceinline__ void mma_bf16(float* c, const uint32_t* a, uint32_t b0, uint32_t b1) {
    asm volatile("mma.sync.aligned.m16n8k16.row.col.f32.bf16.bf16.f32 "
        "{%0,%1,%2,%3}, {%4,%5,%6,%7}, {%8,%9}, {%0,%1,%2,%3};"
        : "+f"(c[0]), "+f"(c[1]), "+f"(c[2]), "+f"(c[3])
        : "r"(a[0]), "r"(a[1]), "r"(a[2]), "r"(a[3]), "r"(b0), "r"(b1));
}

// ============================================================
// Kernel A: xpose (blocks 0..511) + W2 fragment build (block 512)
// ============================================================
__global__ __launch_bounds__(256) void k_front(
    const float* __restrict__ x, const int* __restrict__ mask,
    const float* __restrict__ hW2)
{
    int t = threadIdx.x;
    if (blockIdx.x == 512) {
        for (int e = t; e < 2048; e += 256) {
            int s = e >> 5, lane = e & 31;
            int seg = s >> 5, kt = (s >> 2) & 7, nt = s & 3;
            int k0 = kt * 16 + (lane & 3) * 2;
            int n  = nt * 8 + (lane >> 2);
            float v[4];
            v[0] = hW2[k0 * 32 + n];
            v[1] = hW2[(k0 + 1) * 32 + n];
            v[2] = hW2[(k0 + 8) * 32 + n];
            v[3] = hW2[(k0 + 9) * 32 + n];
            float sv[4];
            #pragma unroll
            for (int i = 0; i < 4; i++) {
                float vh = __bfloat162float(__float2bfloat16(v[i]));
                sv[i] = (seg == 0) ? vh : (v[i] - vh);
            }
            uint32_t b0 = cvt_bf16x2(sv[0], sv[1]);
            uint32_t b1 = cvt_bf16x2(sv[2], sv[3]);
            g_wfrag[e] = (ull)b0 | ((ull)b1 << 32);
        }
        return;
    }
    __shared__ float tx[32][33];
    __shared__ float tm[32][33];
    int jbase = blockIdx.x * 32;
    #pragma unroll
    for (int r = 0; r < 4; r++) {
        int b  = (t >> 5) + r * 8;
        int jj = t & 31;
        tx[b][jj] = x[b * J_ + jbase + jj];
        tm[b][jj] = (float)mask[b * J_ + jbase + jj];
    }
    __syncthreads();
    #pragma unroll
    for (int r = 0; r < 4; r++) {
        int jj = (t >> 5) + r * 8;
        int b  = t & 31;
        g_xT[(jbase + jj) * B_ + b] = tx[b][jj];
        g_mT[(jbase + jj) * B_ + b] = tm[b][jj];
    }
}

// ============================================================
// Kernel B: precg[j][k] + per-j centered LN helper sums.
// ============================================================
__global__ __launch_bounds__(128) void k_pre(
    const float* __restrict__ feat_emb, const float* __restrict__ atse_emb,
    const int* __restrict__ atse_idx, const float* __restrict__ hW1,
    const float* __restrict__ hb1, const float* __restrict__ hg1,
    const float* __restrict__ hB1)
{
    __shared__ __align__(16) float sfeat[PJT][48];
    __shared__ int sidx[PJT];
    __shared__ __align__(16) float sP[PJT][H_];
    __shared__ __align__(16) float sw0c[H_];
    __shared__ float sred[4];
    int k = threadIdx.x;
    int w = k >> 5, lane = k & 31;
    int jbase = blockIdx.x * PJT;

    float wv = hW1[k];
    float s = wv;
    #pragma unroll
    for (int o = 16; o; o >>= 1) s += __shfl_xor_sync(0xffffffffu, s, o);
    if (lane == 0) sred[w] = s;
    if (k < PJT) sidx[k] = atse_idx[jbase + k];
    __syncthreads();
    float mean0 = (sred[0] + sred[1] + sred[2] + sred[3]) * (1.f / H_);
    float w0c = wv - mean0;
    sw0c[k] = w0c;
    if (blockIdx.x == 0) {
        float ss = w0c * w0c;
        #pragma unroll
        for (int o = 16; o; o >>= 1) ss += __shfl_xor_sync(0xffffffffu, ss, o);
        __syncthreads();
        if (lane == 0) sred[w] = ss;
        __syncthreads();
        if (k == 0) g_swwc = sred[0] + sred[1] + sred[2] + sred[3];
        if (k < 64) {
            g_wb[2 * k]     = packf(sw0c[2 * k] * hg1[2 * k], sw0c[2 * k + 1] * hg1[2 * k + 1]);
            g_wb[2 * k + 1] = packf(hB1[2 * k], hB1[2 * k + 1]);
        }
    }

    for (int e = k; e < PJT * 48; e += 128) {
        int jj = e / 48, i = e % 48;
        sfeat[jj][i] = (i < 32) ? feat_emb[(jbase + jj) * 32 + i]
                                : atse_emb[sidx[jj] * 16 + (i - 32)];
    }

    ull wp[24];
    #pragma unroll
    for (int ip = 0; ip < 24; ip++)
        wp[ip] = packf(hW1[(1 + 2 * ip) * H_ + k], hW1[(2 + 2 * ip) * H_ + k]);
    float bk = hb1[k];
    __syncthreads();

    #pragma unroll 2
    for (int jj = 0; jj < PJT; jj++) {
        ull a0 = packf(bk, 0.f), a1 = packf(0.f, 0.f);
        const ull* f = (const ull*)&sfeat[jj][0];
        #pragma unroll
        for (int ip = 0; ip < 12; ip++) {
            a0 = ffma2(f[ip], wp[ip], a0);
            a1 = ffma2(f[ip + 12], wp[ip + 12], a1);
        }
        float l0, h0, l1, h1;
        UNPK(l0, h0, a0); UNPK(l1, h1, a1);
        sP[jj][k] = (l0 + h0) + (l1 + h1);
    }
    __syncthreads();

    #pragma unroll
    for (int r = 0; r < PJT / 4; r++) {
        int jj = w + 4 * r;
        int j = jbase + jj;
        float4 p4 = *(const float4*)&sP[jj][lane * 4];
        float sp = p4.x + p4.y + p4.z + p4.w;
        #pragma unroll
        for (int o = 16; o; o >>= 1) sp += __shfl_xor_sync(0xffffffffu, sp, o);
        float mval = sp * (1.f / H_);
        float c0 = p4.x - mval, c1 = p4.y - mval, c2 = p4.z - mval, c3 = p4.w - mval;
        float4 w4 = *(const float4*)&sw0c[lane * 4];
        float4 g4 = *(const float4*)&hg1[lane * 4];
        float4 pg; pg.x = c0 * g4.x; pg.y = c1 * g4.y; pg.z = c2 * g4.z; pg.w = c3 * g4.w;
        *(float4*)&g_pre1[j * H_ + lane * 4] = pg;
        float ss = c0 * c0 + c1 * c1 + c2 * c2 + c3 * c3;
        float sw = c0 * w4.x + c1 * w4.y + c2 * w4.z + c3 * w4.w;
        #pragma unroll
        for (int o = 16; o; o >>= 1) {
            ss += __shfl_xor_sync(0xffffffffu, ss, o);
            sw += __shfl_xor_sync(0xffffffffu, sw, o);
        }
        if (lane == 0) { g_sppc[j] = ss; g_spwc[j] = sw; }
    }
}

// ============================================================
// Kernel C (hot, mma.sync): block = 64 thr (2 warps). warp <-> one j,
// lane <-> b. 3-term bf16 split on HMMA. Epilogue on fragments.
// (byte-identical to the 84.4us champion)
// ============================================================
__global__ __launch_bounds__(64) void k_main_mma(
    const float* __restrict__ hb2,
    const float* __restrict__ hg2, const float* __restrict__ hB2)
{
    __shared__ __align__(16) char sA[2 * 64 * PITCH];
    __shared__ __align__(16) float spre[2][H_];
    __shared__ __align__(16) ull  swb[H_];

    int t = threadIdx.x, w = t >> 5, lane = t & 31;
    int g = lane >> 2, tg = lane & 3;

    for (int e = t; e < H_; e += 64) swb[e] = g_wb[e];

    float hb2v[8], g2v[8], B2v[8];
    #pragma unroll
    for (int i = 0; i < 8; i++) {
        int d = (i >> 1) * 8 + tg * 2 + (i & 1);
        hb2v[i] = __ldg(hb2 + d);
        g2v[i]  = __ldg(hg2 + d);
        B2v[i]  = __ldg(hB2 + d);
    }
    float swwc = g_swwc;

    uint32_t sA_u = smem_u32(sA);
    char* rowHp = sA + (w * 32 + lane) * PITCH;
    char* rowLp = rowHp + A_LO_OFF;
    uint32_t lmB0 = sA_u + (w * 32 + (lane & 15)) * PITCH + ((lane >> 4) << 4);
    uint32_t lmB1 = lmB0 + 16 * PITCH;

    float poolA[2][8], poolB[2][8];
    #pragma unroll
    for (int mt = 0; mt < 2; mt++)
        #pragma unroll
        for (int i = 0; i < 8; i++) { poolA[mt][i] = 0.f; poolB[mt][i] = 0.f; }
    float cacc[2][2] = {{0.f, 0.f}, {0.f, 0.f}};

    __syncthreads();

    for (int jp = blockIdx.x; jp < NPAIR; jp += MM_BLOCKS) {
        int j = 2 * jp + w;
        float4 p4 = ((const float4*)(g_pre1 + j * H_))[lane];
        *(float4*)((char*)spre[w] + lane * 16) = p4;
        float xb = g_xT[j * B_ + lane];
        float ev = fmaf(xb, fmaf(xb, swwc, 2.f * g_spwc[j]), g_sppc[j]) * (1.f / H_);
        float rs = rsqrtf(ev + EPS_);
        ull xb2 = pack2(xb), rs2 = pack2(rs);
        __syncwarp();

        const ull* pre = (const ull*)spre[w];
        #pragma unroll
        for (int q = 0; q < 16; q++) {
            uint32_t hw[4], lw[4];
            #pragma unroll
            for (int pp = 0; pp < 4; pp++) {
                int p = q * 4 + pp;
                ull tt = ffma2(xb2, swb[2 * p], pre[p]);
                ull hf = ffma2(tt, rs2, swb[2 * p + 1]);
                float f0, f1; UNPK(f0, f1, hf);
                f0 = fmaxf(f0, 0.f); f1 = fmaxf(f1, 0.f);
                uint32_t hi = cvt_bf16x2(f0, f1);
                float d0 = __uint_as_float(hi << 16);
                float d1 = __uint_as_float(hi & 0xFFFF0000u);
                lw[pp] = cvt_bf16x2(f0 - d0, f1 - d1);
                hw[pp] = hi;
            }
            *(uint4*)(rowHp + q * 16) = make_uint4(hw[0], hw[1], hw[2], hw[3]);
            *(uint4*)(rowLp + q * 16) = make_uint4(lw[0], lw[1], lw[2], lw[3]);
        }
        __syncwarp();

        float dacc[2][4][4];
        #pragma unroll
        for (int mt = 0; mt < 2; mt++)
            #pragma unroll
            for (int nt = 0; nt < 4; nt++)
                #pragma unroll
                for (int c = 0; c < 4; c++) dacc[mt][nt][c] = 0.f;

        #pragma unroll
        for (int kt = 0; kt < 8; kt++) {
            uint32_t ah0[4], ah1[4], al0[4], al1[4];
            LDSM4(ah0, lmB0 + kt * 32);
            LDSM4(ah1, lmB1 + kt * 32);
            LDSM4(al0, lmB0 + A_LO_OFF + kt * 32);
            LDSM4(al1, lmB1 + A_LO_OFF + kt * 32);
            #pragma unroll
            for (int nt = 0; nt < 4; nt++) {
                ull vH = __ldg(&g_wfrag[(kt * 4 + nt) * 32 + lane]);
                ull vL = __ldg(&g_wfrag[(32 + kt * 4 + nt) * 32 + lane]);
                uint32_t bh0 = (uint32_t)vH, bh1 = (uint32_t)(vH >> 32);
                uint32_t bl0 = (uint32_t)vL, bl1 = (uint32_t)(vL >> 32);
                mma_bf16(dacc[0][nt], ah0, bh0, bh1);
                mma_bf16(dacc[0][nt], ah0, bl0, bl1);
                mma_bf16(dacc[0][nt], al0, bh0, bh1);
                mma_bf16(dacc[1][nt], ah1, bh0, bh1);
                mma_bf16(dacc[1][nt], ah1, bl0, bl1);
                mma_bf16(dacc[1][nt], al1, bh0, bh1);
            }
        }

        #pragma unroll
        for (int mt = 0; mt < 2; mt++) {
            float oA[8], oB[8];
            #pragma unroll
            for (int i = 0; i < 8; i++) {
                int nt = i >> 1, c = i & 1;
                oA[i] = dacc[mt][nt][c] + hb2v[i];
                oB[i] = dacc[mt][nt][2 + c] + hb2v[i];
            }
            float s1A = 0.f, s2A = 0.f, s1B = 0.f, s2B = 0.f;
            #pragma unroll
            for (int i = 0; i < 8; i++) {
                s1A += oA[i]; s2A = fmaf(oA[i], oA[i], s2A);
                s1B += oB[i]; s2B = fmaf(oB[i], oB[i], s2B);
            }
            s1A += __shfl_xor_sync(0xffffffffu, s1A, 1);
            s1A += __shfl_xor_sync(0xffffffffu, s1A, 2);
            s2A += __shfl_xor_sync(0xffffffffu, s2A, 1);
            s2A += __shfl_xor_sync(0xffffffffu, s2A, 2);
            s1B += __shfl_xor_sync(0xffffffffu, s1B, 1);
            s1B += __shfl_xor_sync(0xffffffffu, s1B, 2);
            s2B += __shfl_xor_sync(0xffffffffu, s2B, 1);
            s2B += __shfl_xor_sync(0xffffffffu, s2B, 2);
            float mA = s1A * (1.f / 32.f);
            float rA = rsqrtf(s2A * (1.f / 32.f) - mA * mA + EPS_);
            float mB = s1B * (1.f / 32.f);
            float rB = rsqrtf(s2B * (1.f / 32.f) - mB * mB + EPS_);
            float mkA = g_mT[j * B_ + mt * 16 + g];
            float mkB = g_mT[j * B_ + mt * 16 + 8 + g];
            if (tg == 0) { cacc[mt][0] += mkA; cacc[mt][1] += mkB; }
            #pragma unroll
            for (int i = 0; i < 8; i++) {
                float eA = fmaxf(fmaf((oA[i] - mA) * rA, g2v[i], B2v[i]), 0.f);
                float eB = fmaxf(fmaf((oB[i] - mB) * rB, g2v[i], B2v[i]), 0.f);
                poolA[mt][i] = fmaf(mkA, eA, poolA[mt][i]);
                poolB[mt][i] = fmaf(mkB, eB, poolB[mt][i]);
            }
        }
    }

    __syncthreads();
    float* sred = (float*)sA;
    float* scnt = (float*)(sA + 8192);
    #pragma unroll
    for (int i = 0; i < 32; i++) {
        int mt = i >> 4, h = (i >> 3) & 1, ii = i & 7;
        sred[(w * 32 + lane) * 32 + i] = h ? poolB[mt][ii] : poolA[mt][ii];
    }
    if (tg == 0) {
        #pragma unroll
        for (int mt = 0; mt < 2; mt++) {
            scnt[w * 32 + mt * 16 + g]     = cacc[mt][0];
            scnt[w * 32 + mt * 16 + 8 + g] = cacc[mt][1];
        }
    }
    __syncthreads();
    if (w == 0) {
        #pragma unroll
        for (int i = 0; i < 32; i++) {
            float s = sred[lane * 32 + i] + sred[(32 + lane) * 32 + i];
            int mt = i >> 4, h = (i >> 3) & 1, ii = i & 7, nt = ii >> 1, c = ii & 1;
            int b = mt * 16 + (h ? 8 : 0) + g;
            int d = nt * 8 + tg * 2 + c;
            g_part[blockIdx.x * (B_ * D_) + b * D_ + d] = s;
        }
        g_cnt[blockIdx.x * B_ + lane] = scnt[lane] + scnt[32 + lane];
    }
}

// ============================================================
// Kernel D (fused reduce+final): one block per b. Reduce this b's
// slice of g_part/g_cnt (fixed order, deterministic), then encoder MLP.
// ============================================================
__device__ __forceinline__ float block_reduce256(float v, float* red, int t) {
    red[t] = v; __syncthreads();
    #pragma unroll
    for (int s = 128; s > 0; s >>= 1) {
        if (t < s) red[t] += red[t + s];
        __syncthreads();
    }
    float r = red[0]; __syncthreads();
    return r;
}

__global__ __launch_bounds__(256) void k_final(
    const float* __restrict__ eW1, const float* __restrict__ eb1,
    const float* __restrict__ eg1, const float* __restrict__ eB1,
    const float* __restrict__ eW2, const float* __restrict__ eb2,
    const float* __restrict__ eg2, const float* __restrict__ eB2,
    float* __restrict__ out)
{
    int b = blockIdx.x, t = threadIdx.x;
    __shared__ float red[256];
    __shared__ float sraw[D_];
    __shared__ float sc[D_];
    __shared__ float se[EH_];
    __shared__ float sml[64];

    // ---- reduce pooled partials for this b (coalesced, 8 chunks) ----
    int d = t & 31, c = t >> 5;
    float s = 0.f;
    for (int blk = c; blk < MM_BLOCKS; blk += 8)
        s += g_part[blk * (B_ * D_) + b * D_ + d];
    red[t] = s;
    __syncthreads();
    if (c == 0) {
        float tot = 0.f;
        #pragma unroll
        for (int cc = 0; cc < 8; cc++) tot += red[cc * 32 + d];
        sraw[d] = tot;
    }
    __syncthreads();

    // ---- reduce counts for this b ----
    float cm = 0.f;
    for (int blk = t; blk < MM_BLOCKS; blk += 256) cm += g_cnt[blk * B_ + b];
    float cnt = block_reduce256(cm, red, t);

    if (t < D_) sc[t] = sraw[t] / fmaxf(cnt, 1.f);
    __syncthreads();

    // ---- encoder MLP ----
    float pe = eb1[t];
    #pragma unroll
    for (int k = 0; k < D_; k++) pe = fmaf(sc[k], eW1[k * EH_ + t], pe);
    float s1 = block_reduce256(pe, red, t);
    float s2 = block_reduce256(pe * pe, red, t);
    float m  = s1 * (1.f / EH_);
    float v  = s2 * (1.f / EH_) - m * m;
    float rs = rsqrtf(v + EPS_);
    se[t] = fmaxf(fmaf((pe - m) * rs, eg1[t], eB1[t]), 0.f);
    __syncthreads();

    if (t < 64) {
        float pm = eb2[t];
        for (int k = 0; k < EH_; k++) pm = fmaf(se[k], eW2[k * 64 + t], pm);
        sml[t] = pm;
    }
    __syncthreads();
    if (t < 64) {
        float a = 0.f, q = 0.f;
        #pragma unroll
        for (int k = 0; k < 64; k++) { a += sml[k]; q = fmaf(sml[k], sml[k], q); }
        float mm = a * (1.f / 64.f);
        float vv = q * (1.f / 64.f) - mm * mm;
        float rr = rsqrtf(vv + EPS_);
        float ml = fmaxf(fmaf((sml[t] - mm) * rr, eg2[t], eB2[t]), 0.f);
        int off = (t < 32) ? (b * 32 + t) : (B_ * 32 + b * 32 + (t - 32));
        out[off] = ml;
    }
}

// ============================================================
extern "C" void kernel_launch(void* const* d_in, const int* in_sizes, int n_in,
                              void* d_out, int out_size) {
    const float* x         = (const float*)d_in[0];
    const int*   mask      = (const int*)  d_in[1];
    const int*   atse_idx  = (const int*)  d_in[2];
    const float* feat_emb  = (const float*)d_in[3];
    const float* atse_emb  = (const float*)d_in[4];
    const float* hW1       = (const float*)d_in[5];
    const float* hb1       = (const float*)d_in[6];
    const float* hg1       = (const float*)d_in[7];
    const float* hB1       = (const float*)d_in[8];
    const float* hW2       = (const float*)d_in[9];
    const float* hb2       = (const float*)d_in[10];
    const float* hg2       = (const float*)d_in[11];
    const float* hB2       = (const float*)d_in[12];
    const float* eW1       = (const float*)d_in[13];
    const float* eb1       = (const float*)d_in[14];
    const float* eg1       = (const float*)d_in[15];
    const float* eB1       = (const float*)d_in[16];
    const float* eW2       = (const float*)d_in[17];
    const float* eb2       = (const float*)d_in[18];
    const float* eg2       = (const float*)d_in[19];
    const float* eB2       = (const float*)d_in[20];
    float* out = (float*)d_out;

    k_front<<<513, 256>>>(x, mask, hW2);
    k_pre<<<J_ / PJT, 128>>>(feat_emb, atse_emb, atse_idx, hW1, hb1, hg1, hB1);
    k_main_mma<<<MM_BLOCKS, 64>>>(hb2, hg2, hB2);
    k_final<<<B_, 256>>>(eW1, eb1, eg1, eB1, eW2, eb2, eg2, eB2, out);
}